// round 17
// baseline (speedup 1.0000x reference)
#include <cuda_runtime.h>
#include <cuda_fp16.h>

#define NUM_B 2
#define NUM_H 32
#define SEQ   2048
#define HD    128
#define BM    128                // q rows per CTA (4 warps x 32 rows)
#define BN    64
#define NTHREADS 128
#define PREP_T   256
#define NTILES (SEQ/BN)          // 32 key tiles per (b,h)

// K/Q fp16 permuted layout: [row][perm(dim)], row stride 144 halves (288 B)
#define KHSTR 144
#define KHIMG (BN*KHSTR)         // 9216 halves per 64-row tile
#define KBYTES (KHIMG*2)         // 18432

// V fp16 permuted layout: [dim][perm(key)], row stride 80 halves (160 B)
#define VHSTR 80
#define VHIMG (HD*VHSTR)         // 10240 halves
#define VBYTES (VHIMG*2)         // 20480

#define QBYTES (2*KBYTES)        // 128-row Q image = 2 consecutive 64-row tiles
#define KV_OFF QBYTES
#define SLOT   (KBYTES + VBYTES) // 38912
#define SMEM_BYTES (QBYTES + 2*SLOT)   // 114688 -> 2 CTAs/SM

// prep smem: raw K + V + Q tiles, row stride 132 floats
#define PSR 132
#define PREP_SMEM_BYTES (3*BN*PSR*4)

// Pre-packed fp16 scratch (device globals: allocation-free)
__device__ __half g_Q2[(size_t)NUM_B*NUM_H*NTILES*KHIMG];   // ~37.7 MB (pre-scaled)
__device__ __half g_K2[(size_t)NUM_B*NUM_H*NTILES*KHIMG];   // ~37.7 MB
__device__ __half g_V2[(size_t)NUM_B*NUM_H*NTILES*VHIMG];   // ~41.9 MB

__device__ __forceinline__ float ex2f(float x){
    float r; asm("ex2.approx.f32 %0, %1;" : "=f"(r) : "f"(x)); return r;
}
__device__ __forceinline__ unsigned packh2(float a, float b){
    __half2 h = __float22half2_rn(make_float2(a, b));
    return *(unsigned*)&h;
}
__device__ __forceinline__ void mma_f16(float c[4], const unsigned a[4],
                                        unsigned b0, unsigned b1){
    asm volatile("mma.sync.aligned.m16n8k16.row.col.f32.f16.f16.f32 "
                 "{%0,%1,%2,%3},{%4,%5,%6,%7},{%8,%9},{%0,%1,%2,%3};"
                 : "+f"(c[0]),"+f"(c[1]),"+f"(c[2]),"+f"(c[3])
                 : "r"(a[0]),"r"(a[1]),"r"(a[2]),"r"(a[3]),"r"(b0),"r"(b1));
}
__device__ __forceinline__ void mbar_wait(unsigned bar, unsigned parity){
    asm volatile(
        "{\n\t"
        ".reg .pred P1;\n\t"
        "W_%=:\n\t"
        "mbarrier.try_wait.parity.acquire.cta.shared::cta.b64 P1, [%0], %1, 0x989680;\n\t"
        "@P1 bra.uni D_%=;\n\t"
        "bra.uni W_%=;\n\t"
        "D_%=:\n\t"
        "}"
        :: "r"(bar), "r"(parity) : "memory");
}

// ===== prep: raw fp32 -> fp16 permuted Q'(scaled)/K'/V' (all global I/O coalesced) =====
__global__ void __launch_bounds__(PREP_T, 1)
prep_kv(const float* __restrict__ Q, const float* __restrict__ K,
        const float* __restrict__ V)
{
    extern __shared__ float ps[];
    float* sk = ps;                // raw K tile: [64][PSR]
    float* sv = ps +   BN*PSR;     // raw V tile
    float* sq = ps + 2*BN*PSR;     // raw Q tile

    const int tile = blockIdx.x, h = blockIdx.y, b = blockIdx.z;
    const int tid  = threadIdx.x;
    const size_t src = ((size_t)(b*NUM_H + h)*SEQ + (size_t)tile*BN) * HD;
    __half* qd = g_Q2 + ((size_t)(b*NUM_H + h)*NTILES + tile) * KHIMG;
    __half* kd = g_K2 + ((size_t)(b*NUM_H + h)*NTILES + tile) * KHIMG;
    __half* vd = g_V2 + ((size_t)(b*NUM_H + h)*NTILES + tile) * VHIMG;

    const unsigned skb = (unsigned)__cvta_generic_to_shared(sk);
    const unsigned svb = (unsigned)__cvta_generic_to_shared(sv);
    const unsigned sqb = (unsigned)__cvta_generic_to_shared(sq);

    #pragma unroll
    for (int i = 0; i < (BN*HD/4)/PREP_T; i++){
        int idx = tid + i*PREP_T;
        int row = idx >> 5;
        int c4  = (idx & 31) * 4;
        asm volatile("cp.async.cg.shared.global [%0], [%1], 16;"
                     :: "r"(skb + (unsigned)((row*PSR + c4)*4)),
                        "l"(K + src + (size_t)row*HD + c4));
        asm volatile("cp.async.cg.shared.global [%0], [%1], 16;"
                     :: "r"(svb + (unsigned)((row*PSR + c4)*4)),
                        "l"(V + src + (size_t)row*HD + c4));
        asm volatile("cp.async.cg.shared.global [%0], [%1], 16;"
                     :: "r"(sqb + (unsigned)((row*PSR + c4)*4)),
                        "l"(Q + src + (size_t)row*HD + c4));
    }
    asm volatile("cp.async.commit_group;");
    asm volatile("cp.async.wait_group 0;");
    __syncthreads();

    const float SCALE2 = 0.08838834764831845f * 1.4426950408889634f;

    // K' and Q': [row][perm(dim)]; per 16-dim block t: {2c0,2c0+1,2c0+8,2c0+9} at 4c0
    #pragma unroll
    for (int i = 0; i < 4; i++){
        int idx = tid + i*PREP_T;            // 64 rows x 16 subgroups
        int row = idx >> 4;
        int s   = idx & 15;
        int t   = s >> 1;
        int u   = s & 1;
        int kb  = 16*t + 4*u;
        const float* spk = sk + row*PSR;
        uint4 o4;
        o4.x = packh2(spk[kb+0 ], spk[kb+1 ]);
        o4.y = packh2(spk[kb+8 ], spk[kb+9 ]);
        o4.z = packh2(spk[kb+2 ], spk[kb+3 ]);
        o4.w = packh2(spk[kb+10], spk[kb+11]);
        *(uint4*)(kd + row*KHSTR + s*8) = o4;

        const float* spq = sq + row*PSR;
        uint4 q4;
        q4.x = packh2(spq[kb+0 ]*SCALE2, spq[kb+1 ]*SCALE2);
        q4.y = packh2(spq[kb+8 ]*SCALE2, spq[kb+9 ]*SCALE2);
        q4.z = packh2(spq[kb+2 ]*SCALE2, spq[kb+3 ]*SCALE2);
        q4.w = packh2(spq[kb+10]*SCALE2, spq[kb+11]*SCALE2);
        *(uint4*)(qd + row*KHSTR + s*8) = q4;
    }

    // V': [dim][perm(key)], same 16-block permutation over keys
    #pragma unroll
    for (int i = 0; i < 4; i++){
        int idx = tid + i*PREP_T;            // 128 dims x 8 subgroups
        int dim = idx >> 3;
        int s   = idx & 7;
        int t   = s >> 1;
        int u   = s & 1;
        int kb  = 16*t + 4*u;
        const float* sp = sv + dim;
        uint4 o4;
        o4.x = packh2(sp[(kb+0 )*PSR], sp[(kb+1 )*PSR]);
        o4.y = packh2(sp[(kb+8 )*PSR], sp[(kb+9 )*PSR]);
        o4.z = packh2(sp[(kb+2 )*PSR], sp[(kb+3 )*PSR]);
        o4.w = packh2(sp[(kb+10)*PSR], sp[(kb+11)*PSR]);
        *(uint4*)(vd + dim*VHSTR + s*8) = o4;
    }
}

// ============================ main attention ============================
__global__ void __launch_bounds__(NTHREADS, 2)
fa_fwd(float* __restrict__ Out)
{
    extern __shared__ char smc[];
    __shared__ unsigned long long s_mbar[3];   // [0,1]=kv stages, [2]=Q
    const __half* Qs = (const __half*)smc;                 // 128 x KHSTR
    __half* Ks = (__half*)(smc + KV_OFF);                  // stage base (K then V per slot)

    const int tid  = threadIdx.x;
    const int warp = tid >> 5;                 // 0..3
    const int lane = tid & 31;
    const int r0   = lane >> 2;
    const int c0   = lane & 3;

    // heavy-first: largest qb gets earliest block ids
    const int qb = (SEQ/BM - 1) - blockIdx.x;  // 0..15
    const int h = blockIdx.y, b = blockIdx.z;
    const int qbase = qb * BM;
    const size_t bhT = (size_t)(b*NUM_H + h) * NTILES;

    const unsigned smb = (unsigned)__cvta_generic_to_shared(smc);
    const unsigned mb0 = (unsigned)__cvta_generic_to_shared(&s_mbar[0]);
    const unsigned mb1 = (unsigned)__cvta_generic_to_shared(&s_mbar[1]);
    const unsigned mbq = (unsigned)__cvta_generic_to_shared(&s_mbar[2]);

    if (tid == 0){
        asm volatile("mbarrier.init.shared.b64 [%0], 1;" :: "r"(mb0) : "memory");
        asm volatile("mbarrier.init.shared.b64 [%0], 1;" :: "r"(mb1) : "memory");
        asm volatile("mbarrier.init.shared.b64 [%0], 1;" :: "r"(mbq) : "memory");
    }
    __syncthreads();

    const int jmax = 2*qb + 1;   // causal: key tiles 0..jmax

    auto load_tiles = [&](int j, int buf){
        if (tid == 0){
            unsigned bar = buf ? mb1 : mb0;
            const __half* kg = g_K2 + (bhT + j)*KHIMG;
            const __half* vg = g_V2 + (bhT + j)*VHIMG;
            unsigned dst = smb + KV_OFF + (unsigned)(buf*SLOT);
            asm volatile("mbarrier.arrive.expect_tx.shared.b64 _, [%0], %1;"
                         :: "r"(bar), "r"(SLOT) : "memory");
            asm volatile("cp.async.bulk.shared::cluster.global.mbarrier::complete_tx::bytes "
                         "[%0], [%1], %2, [%3];"
                         :: "r"(dst), "l"(kg), "r"(KBYTES), "r"(bar) : "memory");
            asm volatile("cp.async.bulk.shared::cluster.global.mbarrier::complete_tx::bytes "
                         "[%0], [%1], %2, [%3];"
                         :: "r"(dst + KBYTES), "l"(vg), "r"(VBYTES), "r"(bar) : "memory");
        }
    };

    // prologue: Q DMA (2 consecutive 64-row tiles = contiguous) + first KV tile
    if (tid == 0){
        const __half* qg = g_Q2 + (bhT + 2*qb)*KHIMG;
        asm volatile("mbarrier.arrive.expect_tx.shared.b64 _, [%0], %1;"
                     :: "r"(mbq), "r"(QBYTES) : "memory");
        asm volatile("cp.async.bulk.shared::cluster.global.mbarrier::complete_tx::bytes "
                     "[%0], [%1], %2, [%3];"
                     :: "r"(smb), "l"(qg), "r"(QBYTES), "r"(mbq) : "memory");
    }
    load_tiles(0, 0);
    mbar_wait(mbq, 0u);          // Q resident for the whole kernel

    // O accumulators: 2 m-tiles x 16 dim-tiles x 4 = 128 regs
    float oA[16][4], oB[16][4];
    #pragma unroll
    for (int i = 0; i < 16; i++){
        oA[i][0]=0.f; oA[i][1]=0.f; oA[i][2]=0.f; oA[i][3]=0.f;
        oB[i][0]=0.f; oB[i][1]=0.f; oB[i][2]=0.f; oB[i][3]=0.f;
    }
    float mA0=-1e30f, mA1=-1e30f, mB0=-1e30f, mB1=-1e30f;
    float lA0=0.f, lA1=0.f, lB0=0.f, lB1=0.f;

    const __half* Qw = Qs + (warp*32)*KHSTR + 4*c0;
    const int qrA0 = qbase + warp*32 + r0;       // m-tile A rows
    const int qrB0 = qrA0 + 16;                  // m-tile B rows

    for (int j = 0; j <= jmax; j++){
        const int cur = j & 1;
        mbar_wait(cur ? mb1 : mb0, (j >> 1) & 1);   // tile j landed (acquire)
        __syncthreads();                             // all warps done with tile j-1
        if (j < jmax) load_tiles(j + 1, cur ^ 1);

        const __half* Kb = (const __half*)(smc + KV_OFF + cur*SLOT);
        const __half* Vb = (const __half*)(smc + KV_OFF + cur*SLOT + KBYTES);

        // ===== S = Q*K^T, two m-tiles sharing every K-fragment =====
        float sA[8][4], sB[8][4];
        #pragma unroll
        for (int i = 0; i < 8; i++){
            sA[i][0]=0.f; sA[i][1]=0.f; sA[i][2]=0.f; sA[i][3]=0.f;
            sB[i][0]=0.f; sB[i][1]=0.f; sB[i][2]=0.f; sB[i][3]=0.f;
        }
        #pragma unroll
        for (int t = 0; t < 8; t++){
            const __half* qp = Qw + t*16;
            uint2 uA0 = *(const uint2*)(qp + (r0     )*KHSTR);
            uint2 uA1 = *(const uint2*)(qp + (r0 +  8)*KHSTR);
            uint2 uB0 = *(const uint2*)(qp + (r0 + 16)*KHSTR);
            uint2 uB1 = *(const uint2*)(qp + (r0 + 24)*KHSTR);
            unsigned qfA[4] = {uA0.x, uA1.x, uA0.y, uA1.y};
            unsigned qfB[4] = {uB0.x, uB1.x, uB0.y, uB1.y};
            #pragma unroll
            for (int nt = 0; nt < 8; nt++){
                uint2 kf = *(const uint2*)(Kb + (8*nt + r0)*KHSTR + t*16 + 4*c0);
                mma_f16(sA[nt], qfA, kf.x, kf.y);
                mma_f16(sB[nt], qfB, kf.x, kf.y);
            }
        }

        // ===== causal mask (last two tiles) + row max, both m-tiles =====
        const bool maskblk = (j*BN + BN) > qbase;
        float rA0=-1e30f, rA1=-1e30f, rB0=-1e30f, rB1=-1e30f;
        #pragma unroll
        for (int nt = 0; nt < 8; nt++){
            if (maskblk){
                int colb = j*BN + nt*8 + 2*c0;
                if (colb     > qrA0     ) sA[nt][0] = -1e30f;
                if (colb + 1 > qrA0     ) sA[nt][1] = -1e30f;
                if (colb     > qrA0 + 8 ) sA[nt][2] = -1e30f;
                if (colb + 1 > qrA0 + 8 ) sA[nt][3] = -1e30f;
                if (colb     > qrB0     ) sB[nt][0] = -1e30f;
                if (colb + 1 > qrB0     ) sB[nt][1] = -1e30f;
                if (colb     > qrB0 + 8 ) sB[nt][2] = -1e30f;
                if (colb + 1 > qrB0 + 8 ) sB[nt][3] = -1e30f;
            }
            rA0 = fmaxf(rA0, fmaxf(sA[nt][0], sA[nt][1]));
            rA1 = fmaxf(rA1, fmaxf(sA[nt][2], sA[nt][3]));
            rB0 = fmaxf(rB0, fmaxf(sB[nt][0], sB[nt][1]));
            rB1 = fmaxf(rB1, fmaxf(sB[nt][2], sB[nt][3]));
        }
        rA0 = fmaxf(rA0, __shfl_xor_sync(0xffffffffu, rA0, 1));
        rA0 = fmaxf(rA0, __shfl_xor_sync(0xffffffffu, rA0, 2));
        rA1 = fmaxf(rA1, __shfl_xor_sync(0xffffffffu, rA1, 1));
        rA1 = fmaxf(rA1, __shfl_xor_sync(0xffffffffu, rA1, 2));
        rB0 = fmaxf(rB0, __shfl_xor_sync(0xffffffffu, rB0, 1));
        rB0 = fmaxf(rB0, __shfl_xor_sync(0xffffffffu, rB0, 2));
        rB1 = fmaxf(rB1, __shfl_xor_sync(0xffffffffu, rB1, 1));
        rB1 = fmaxf(rB1, __shfl_xor_sync(0xffffffffu, rB1, 2));

        float mA0n = fmaxf(mA0, rA0), mA1n = fmaxf(mA1, rA1);
        float mB0n = fmaxf(mB0, rB0), mB1n = fmaxf(mB1, rB1);
        float aA0 = ex2f(mA0 - mA0n), aA1 = ex2f(mA1 - mA1n);
        float aB0 = ex2f(mB0 - mB0n), aB1 = ex2f(mB1 - mB1n);
        mA0 = mA0n; mA1 = mA1n; mB0 = mB0n; mB1 = mB1n;

        // ===== P = exp2(S - m), packed fp16 A-fragments; row sums =====
        unsigned paA[4][4], paB[4][4];
        float sAr0 = 0.f, sAr1 = 0.f, sBr0 = 0.f, sBr1 = 0.f;
        #pragma unroll
        for (int t = 0; t < 4; t++){
            float p0 = ex2f(sA[2*t][0] - mA0n);
            float p1 = ex2f(sA[2*t][1] - mA0n);
            float p2 = ex2f(sA[2*t][2] - mA1n);
            float p3 = ex2f(sA[2*t][3] - mA1n);
            float p4 = ex2f(sA[2*t+1][0] - mA0n);
            float p5 = ex2f(sA[2*t+1][1] - mA0n);
            float p6 = ex2f(sA[2*t+1][2] - mA1n);
            float p7 = ex2f(sA[2*t+1][3] - mA1n);
            sAr0 += (p0 + p1) + (p4 + p5);
            sAr1 += (p2 + p3) + (p6 + p7);
            paA[t][0] = packh2(p0, p1);
            paA[t][1] = packh2(p2, p3);
            paA[t][2] = packh2(p4, p5);
            paA[t][3] = packh2(p6, p7);

            float q0 = ex2f(sB[2*t][0] - mB0n);
            float q1 = ex2f(sB[2*t][1] - mB0n);
            float q2 = ex2f(sB[2*t][2] - mB1n);
            float q3 = ex2f(sB[2*t][3] - mB1n);
            float q4 = ex2f(sB[2*t+1][0] - mB0n);
            float q5 = ex2f(sB[2*t+1][1] - mB0n);
            float q6 = ex2f(sB[2*t+1][2] - mB1n);
            float q7 = ex2f(sB[2*t+1][3] - mB1n);
            sBr0 += (q0 + q1) + (q4 + q5);
            sBr1 += (q2 + q3) + (q6 + q7);
            paB[t][0] = packh2(q0, q1);
            paB[t][1] = packh2(q2, q3);
            paB[t][2] = packh2(q4, q5);
            paB[t][3] = packh2(q6, q7);
        }
        sAr0 += __shfl_xor_sync(0xffffffffu, sAr0, 1);
        sAr0 += __shfl_xor_sync(0xffffffffu, sAr0, 2);
        sAr1 += __shfl_xor_sync(0xffffffffu, sAr1, 1);
        sAr1 += __shfl_xor_sync(0xffffffffu, sAr1, 2);
        sBr0 += __shfl_xor_sync(0xffffffffu, sBr0, 1);
        sBr0 += __shfl_xor_sync(0xffffffffu, sBr0, 2);
        sBr1 += __shfl_xor_sync(0xffffffffu, sBr1, 1);
        sBr1 += __shfl_xor_sync(0xffffffffu, sBr1, 2);
        lA0 = lA0*aA0 + sAr0;
        lA1 = lA1*aA1 + sAr1;
        lB0 = lB0*aB0 + sBr0;
        lB1 = lB1*aB1 + sBr1;

        #pragma unroll
        for (int nt = 0; nt < 16; nt++){
            oA[nt][0] *= aA0; oA[nt][1] *= aA0; oA[nt][2] *= aA1; oA[nt][3] *= aA1;
            oB[nt][0] *= aB0; oB[nt][1] *= aB0; oB[nt][2] *= aB1; oB[nt][3] *= aB1;
        }

        // ===== O += P*V, two m-tiles sharing every V-fragment =====
        #pragma unroll
        for (int nt = 0; nt < 16; nt++){
            const uint2* vp = (const uint2*)(Vb + (8*nt + r0)*VHSTR + c0*4);
            uint2 vf[4];
            #pragma unroll
            for (int t = 0; t < 4; t++) vf[t] = vp[t*4];
            #pragma unroll
            for (int t = 0; t < 4; t++){
                mma_f16(oA[nt], paA[t], vf[t].x, vf[t].y);
                mma_f16(oB[nt], paB[t], vf[t].x, vf[t].y);
            }
        }
        // no end barrier: next iter's wait+sync licenses buffer reuse
    }

    // ===== epilogue: normalize + write [b, q, h*D] =====
    float iA0 = 1.f/lA0, iA1 = 1.f/lA1, iB0 = 1.f/lB0, iB1 = 1.f/lB1;
    const size_t ob = (size_t)b * SEQ * NUM_H * HD + (size_t)blockIdx.y * HD;
    #pragma unroll
    for (int nt = 0; nt < 16; nt++){
        int col = nt*8 + 2*c0;
        *(float2*)&Out[ob + (size_t)(qrA0    ) * NUM_H * HD + col] =
            make_float2(oA[nt][0]*iA0, oA[nt][1]*iA0);
        *(float2*)&Out[ob + (size_t)(qrA0 + 8) * NUM_H * HD + col] =
            make_float2(oA[nt][2]*iA1, oA[nt][3]*iA1);
        *(float2*)&Out[ob + (size_t)(qrB0    ) * NUM_H * HD + col] =
            make_float2(oB[nt][0]*iB0, oB[nt][1]*iB0);
        *(float2*)&Out[ob + (size_t)(qrB0 + 8) * NUM_H * HD + col] =
            make_float2(oB[nt][2]*iB1, oB[nt][3]*iB1);
    }
}

extern "C" void kernel_launch(void* const* d_in, const int* in_sizes, int n_in,
                              void* d_out, int out_size)
{
    const float* Q = (const float*)d_in[0];
    const float* K = (const float*)d_in[1];
    const float* V = (const float*)d_in[2];
    float* Out = (float*)d_out;

    cudaFuncSetAttribute(fa_fwd, cudaFuncAttributeMaxDynamicSharedMemorySize, SMEM_BYTES);
    cudaFuncSetAttribute(prep_kv, cudaFuncAttributeMaxDynamicSharedMemorySize, PREP_SMEM_BYTES);

    dim3 pgrid(NTILES, NUM_H, NUM_B);
    prep_kv<<<pgrid, PREP_T, PREP_SMEM_BYTES>>>(Q, K, V);

    dim3 grid(SEQ / BM, NUM_H, NUM_B);
    fa_fwd<<<grid, NTHREADS, SMEM_BYTES>>>(Out);
}